// round 1
// baseline (speedup 1.0000x reference)
#include <cuda_runtime.h>
#include <math.h>

#define BATCH 8
#define CC 512
#define NN 4096
#define GG 32
#define CPG 16

// ---- scratch (static device globals; allowed by harness rules) ----
__device__ float g_q[(size_t)BATCH * CC * NN];      // 64 MB
__device__ float g_k[(size_t)BATCH * CC * NN];      // 64 MB
__device__ float g_att[(size_t)BATCH * CC * NN];    // 64 MB
__device__ float g_s[(size_t)BATCH * NN * NN];      // 512 MB (scores / probs in place)
__device__ float g_stats[BATCH * GG * 2];           // mean, rstd per (b, g)

// ============================================================
// Kernel 1: GroupNorm statistics. One block per (b, g).
// Group g = channels [g*16, g*16+16), each channel 4096 contiguous floats,
// and consecutive channels are contiguous -> one flat 65536-float range.
// ============================================================
__global__ void gn_stats_kernel(const float* __restrict__ x) {
    int b = blockIdx.x, g = blockIdx.y;
    const float* xp = x + ((size_t)(b * CC) + g * CPG) * NN;
    float s = 0.f, s2 = 0.f;
    for (int i = threadIdx.x; i < CPG * NN; i += 256) {
        float v = xp[i];
        s += v;
        s2 += v * v;
    }
    __shared__ float sh[256], sh2[256];
    sh[threadIdx.x] = s;
    sh2[threadIdx.x] = s2;
    __syncthreads();
    for (int off = 128; off > 0; off >>= 1) {
        if (threadIdx.x < off) {
            sh[threadIdx.x] += sh[threadIdx.x + off];
            sh2[threadIdx.x] += sh2[threadIdx.x + off];
        }
        __syncthreads();
    }
    if (threadIdx.x == 0) {
        const float inv = 1.f / (float)(CPG * NN);
        float mu = sh[0] * inv;
        float var = sh2[0] * inv - mu * mu;
        g_stats[(b * GG + g) * 2 + 0] = mu;
        g_stats[(b * GG + g) * 2 + 1] = rsqrtf(var + 1e-6f);
    }
}

// ============================================================
// Kernel 2: q / k projection GEMM with GroupNorm fused on the input side.
//   out[b][o][n] = bias[o] + sum_c w[o][c] * norm(x[b][c][n])
// blockIdx.z = b*2 + which (0 = q, 1 = k). 64x64 output tile, 256 threads,
// 4x4 microtile, K-chunk of 16.
// ============================================================
__global__ void qk_gemm_kernel(const float* __restrict__ x,
                               const float* __restrict__ qw, const float* __restrict__ qb,
                               const float* __restrict__ kw, const float* __restrict__ kb,
                               const float* __restrict__ gamma, const float* __restrict__ beta) {
    int b = blockIdx.z >> 1;
    int which = blockIdx.z & 1;
    const float* w = which ? kw : qw;
    const float* bias = which ? kb : qb;
    float* out = which ? g_k : g_q;

    int n0 = blockIdx.x * 64;
    int o0 = blockIdx.y * 64;

    __shared__ float Ws[16][68];  // [kk][o]
    __shared__ float Rs[16][68];  // [kk][n]

    int tid = threadIdx.x;
    int tx = tid & 15, ty = tid >> 4;
    float acc[4][4] = {};

    const float* xb = x + (size_t)b * CC * NN;

    for (int c0 = 0; c0 < CC; c0 += 16) {
        // load weights, transposed to [kk][o]
        {
            int kk = tid & 15, ob = tid >> 4;
#pragma unroll
            for (int r = 0; r < 4; r++) {
                int o = o0 + ob + r * 16;
                Ws[kk][ob + r * 16] = w[(size_t)o * CC + c0 + kk];
            }
        }
        // load x tile and normalize on the fly -> [kk][n]
        {
            int nj = tid & 63, kbase = tid >> 6;
#pragma unroll
            for (int r = 0; r < 4; r++) {
                int kk = kbase + r * 4;
                int c = c0 + kk;
                int g = c >> 4;
                float mu = g_stats[(b * GG + g) * 2 + 0];
                float rstd = g_stats[(b * GG + g) * 2 + 1];
                float v = xb[(size_t)c * NN + n0 + nj];
                Rs[kk][nj] = (v - mu) * rstd * gamma[c] + beta[c];
            }
        }
        __syncthreads();
#pragma unroll
        for (int kk = 0; kk < 16; kk++) {
            float4 a4 = *reinterpret_cast<const float4*>(&Ws[kk][ty * 4]);
            float4 b4 = *reinterpret_cast<const float4*>(&Rs[kk][tx * 4]);
            float a[4] = {a4.x, a4.y, a4.z, a4.w};
            float bb[4] = {b4.x, b4.y, b4.z, b4.w};
#pragma unroll
            for (int i = 0; i < 4; i++)
#pragma unroll
                for (int j = 0; j < 4; j++) acc[i][j] += a[i] * bb[j];
        }
        __syncthreads();
    }

#pragma unroll
    for (int i = 0; i < 4; i++) {
        int o = o0 + ty * 4 + i;
        float bv = bias[o];
        float* op = out + ((size_t)b * CC + o) * NN + n0 + tx * 4;
        float4 v = make_float4(acc[i][0] + bv, acc[i][1] + bv, acc[i][2] + bv, acc[i][3] + bv);
        *reinterpret_cast<float4*>(op) = v;
    }
}

// ============================================================
// Kernel 3: scores GEMM. S[b][n][m] = scale * sum_c q[b][c][n] * k[b][c][m]
// Both operands are read along their contiguous (n / m) dimension.
// ============================================================
__global__ void scores_gemm_kernel() {
    int b = blockIdx.z;
    int m0 = blockIdx.x * 64;
    int n0 = blockIdx.y * 64;

    __shared__ float Qs[16][68];  // [kk][n]
    __shared__ float Ks[16][68];  // [kk][m]

    int tid = threadIdx.x;
    int tx = tid & 15, ty = tid >> 4;
    float acc[4][4] = {};

    const float* qp = g_q + (size_t)b * CC * NN;
    const float* kp = g_k + (size_t)b * CC * NN;

    for (int c0 = 0; c0 < CC; c0 += 16) {
        int col = tid & 63, kbase = tid >> 6;
#pragma unroll
        for (int r = 0; r < 4; r++) {
            int kk = kbase + r * 4;
            Qs[kk][col] = qp[(size_t)(c0 + kk) * NN + n0 + col];
            Ks[kk][col] = kp[(size_t)(c0 + kk) * NN + m0 + col];
        }
        __syncthreads();
#pragma unroll
        for (int kk = 0; kk < 16; kk++) {
            float4 a4 = *reinterpret_cast<const float4*>(&Qs[kk][ty * 4]);
            float4 b4 = *reinterpret_cast<const float4*>(&Ks[kk][tx * 4]);
            float a[4] = {a4.x, a4.y, a4.z, a4.w};
            float bb[4] = {b4.x, b4.y, b4.z, b4.w};
#pragma unroll
            for (int i = 0; i < 4; i++)
#pragma unroll
                for (int j = 0; j < 4; j++) acc[i][j] += a[i] * bb[j];
        }
        __syncthreads();
    }

    const float scale = rsqrtf((float)CC);
#pragma unroll
    for (int i = 0; i < 4; i++) {
        float* sp = g_s + ((size_t)b * NN + n0 + ty * 4 + i) * NN + m0 + tx * 4;
        float4 v = make_float4(acc[i][0] * scale, acc[i][1] * scale,
                               acc[i][2] * scale, acc[i][3] * scale);
        *reinterpret_cast<float4*>(sp) = v;
    }
}

// ============================================================
// Kernel 4: row softmax over m (4096). One block per (b, n) row.
// Row held fully in registers: 16 values per thread.
// ============================================================
__global__ void softmax_kernel() {
    int b = blockIdx.y;
    int row = blockIdx.x;
    float* p = g_s + ((size_t)b * NN + row) * NN;
    int tid = threadIdx.x;

    float vals[16];
    float mx = -1e30f;
#pragma unroll
    for (int i = 0; i < 16; i++) {
        vals[i] = p[tid + i * 256];
        mx = fmaxf(mx, vals[i]);
    }
    // block max
    __shared__ float sred[64];
#pragma unroll
    for (int off = 16; off > 0; off >>= 1)
        mx = fmaxf(mx, __shfl_xor_sync(0xffffffffu, mx, off));
    if ((tid & 31) == 0) sred[tid >> 5] = mx;
    __syncthreads();
    if (tid < 32) {
        float v = (tid < 8) ? sred[tid] : -1e30f;
#pragma unroll
        for (int off = 4; off > 0; off >>= 1)
            v = fmaxf(v, __shfl_xor_sync(0xffffffffu, v, off));
        if (tid == 0) sred[32] = v;
    }
    __syncthreads();
    mx = sred[32];

    float sum = 0.f;
#pragma unroll
    for (int i = 0; i < 16; i++) {
        vals[i] = __expf(vals[i] - mx);
        sum += vals[i];
    }
#pragma unroll
    for (int off = 16; off > 0; off >>= 1)
        sum += __shfl_xor_sync(0xffffffffu, sum, off);
    if ((tid & 31) == 0) sred[tid >> 5] = sum;
    __syncthreads();
    if (tid < 32) {
        float v = (tid < 8) ? sred[tid] : 0.f;
#pragma unroll
        for (int off = 4; off > 0; off >>= 1)
            v += __shfl_xor_sync(0xffffffffu, v, off);
        if (tid == 0) sred[33] = v;
    }
    __syncthreads();
    float inv = 1.f / sred[33];
#pragma unroll
    for (int i = 0; i < 16; i++) p[tid + i * 256] = vals[i] * inv;
}

// ============================================================
// Kernel 5: AV GEMM. att[b][c][n] = sum_m k[b][c][m] * P[b][n][m]
// Reduction runs along the contiguous dim of both operands, so tiles are
// staged transposed in smem. K-chunk 32.
// ============================================================
__global__ void av_gemm_kernel() {
    int b = blockIdx.z;
    int c0b = blockIdx.y * 64;
    int n0 = blockIdx.x * 64;

    __shared__ float Kt[32][68];  // [mm][c]
    __shared__ float Pt[32][68];  // [mm][n]

    int tid = threadIdx.x;
    int tx = tid & 15, ty = tid >> 4;
    float acc[4][4] = {};

    const float* kp = g_k + (size_t)b * CC * NN;
    const float* pp = g_s + (size_t)b * NN * NN;

    for (int m0 = 0; m0 < NN; m0 += 32) {
        int mm = tid & 31, ib = tid >> 5;
#pragma unroll
        for (int r = 0; r < 8; r++) {
            int idx = ib + r * 8;  // 0..63
            Kt[mm][idx] = kp[(size_t)(c0b + idx) * NN + m0 + mm];
            Pt[mm][idx] = pp[(size_t)(n0 + idx) * NN + m0 + mm];
        }
        __syncthreads();
#pragma unroll
        for (int mm2 = 0; mm2 < 32; mm2++) {
            float4 a4 = *reinterpret_cast<const float4*>(&Kt[mm2][ty * 4]);
            float4 b4 = *reinterpret_cast<const float4*>(&Pt[mm2][tx * 4]);
            float a[4] = {a4.x, a4.y, a4.z, a4.w};
            float bb[4] = {b4.x, b4.y, b4.z, b4.w};
#pragma unroll
            for (int i = 0; i < 4; i++)
#pragma unroll
                for (int j = 0; j < 4; j++) acc[i][j] += a[i] * bb[j];
        }
        __syncthreads();
    }

#pragma unroll
    for (int i = 0; i < 4; i++) {
        int c = c0b + ty * 4 + i;
        float* op = g_att + ((size_t)b * CC + c) * NN + n0 + tx * 4;
        float4 v = make_float4(acc[i][0], acc[i][1], acc[i][2], acc[i][3]);
        *reinterpret_cast<float4*>(op) = v;
    }
}

// ============================================================
// Kernel 6: proj GEMM + bias + residual.
//   out[b][o][n] = x[b][o][n] + pb[o] + sum_c pw[o][c] * att[b][c][n]
// ============================================================
__global__ void proj_gemm_kernel(const float* __restrict__ x,
                                 const float* __restrict__ pw,
                                 const float* __restrict__ pb,
                                 float* __restrict__ out) {
    int b = blockIdx.z;
    int n0 = blockIdx.x * 64;
    int o0 = blockIdx.y * 64;

    __shared__ float Ws[16][68];  // [kk][o]
    __shared__ float As[16][68];  // [kk][n]

    int tid = threadIdx.x;
    int tx = tid & 15, ty = tid >> 4;
    float acc[4][4] = {};

    const float* ap = g_att + (size_t)b * CC * NN;

    for (int c0 = 0; c0 < CC; c0 += 16) {
        {
            int kk = tid & 15, ob = tid >> 4;
#pragma unroll
            for (int r = 0; r < 4; r++) {
                int o = o0 + ob + r * 16;
                Ws[kk][ob + r * 16] = pw[(size_t)o * CC + c0 + kk];
            }
        }
        {
            int nj = tid & 63, kbase = tid >> 6;
#pragma unroll
            for (int r = 0; r < 4; r++) {
                int kk = kbase + r * 4;
                As[kk][nj] = ap[(size_t)(c0 + kk) * NN + n0 + nj];
            }
        }
        __syncthreads();
#pragma unroll
        for (int kk = 0; kk < 16; kk++) {
            float4 a4 = *reinterpret_cast<const float4*>(&Ws[kk][ty * 4]);
            float4 b4 = *reinterpret_cast<const float4*>(&As[kk][tx * 4]);
            float a[4] = {a4.x, a4.y, a4.z, a4.w};
            float bb[4] = {b4.x, b4.y, b4.z, b4.w};
#pragma unroll
            for (int i = 0; i < 4; i++)
#pragma unroll
                for (int j = 0; j < 4; j++) acc[i][j] += a[i] * bb[j];
        }
        __syncthreads();
    }

#pragma unroll
    for (int i = 0; i < 4; i++) {
        int o = o0 + ty * 4 + i;
        float bv = pb[o];
        size_t base = ((size_t)b * CC + o) * NN + n0 + tx * 4;
        float4 xv = *reinterpret_cast<const float4*>(&x[base]);
        float4 v = make_float4(acc[i][0] + bv + xv.x, acc[i][1] + bv + xv.y,
                               acc[i][2] + bv + xv.z, acc[i][3] + bv + xv.w);
        *reinterpret_cast<float4*>(&out[base]) = v;
    }
}

// ============================================================
// launch
// ============================================================
extern "C" void kernel_launch(void* const* d_in, const int* in_sizes, int n_in,
                              void* d_out, int out_size) {
    const float* x     = (const float*)d_in[0];
    const float* gamma = (const float*)d_in[1];
    const float* beta  = (const float*)d_in[2];
    const float* q_w   = (const float*)d_in[3];
    const float* q_b   = (const float*)d_in[4];
    const float* k_w   = (const float*)d_in[5];
    const float* k_b   = (const float*)d_in[6];
    const float* p_w   = (const float*)d_in[7];
    const float* p_b   = (const float*)d_in[8];
    float* out = (float*)d_out;

    (void)in_sizes; (void)n_in; (void)out_size;

    // 1. GroupNorm stats
    gn_stats_kernel<<<dim3(BATCH, GG), 256>>>(x);

    // 2. q/k projections with fused normalization
    qk_gemm_kernel<<<dim3(NN / 64, CC / 64, BATCH * 2), 256>>>(
        x, q_w, q_b, k_w, k_b, gamma, beta);

    // 3. scores = scale * q^T k
    scores_gemm_kernel<<<dim3(NN / 64, NN / 64, BATCH), 256>>>();

    // 4. softmax over last dim
    softmax_kernel<<<dim3(NN, BATCH), 256>>>();

    // 5. att = v @ attn^T  (v = k)
    av_gemm_kernel<<<dim3(NN / 64, CC / 64, BATCH), 256>>>();

    // 6. out = x + proj(att)
    proj_gemm_kernel<<<dim3(NN / 64, CC / 64, BATCH), 256>>>(x, p_w, p_b, out);
}